// round 1
// baseline (speedup 1.0000x reference)
#include <cuda_runtime.h>

// RestrictedNN: B=4096, N_INP=4096, L0=512 leaves (G=8 genes each, H=16),
// L1=64 (128->16), L2=8 (128->16), root 128->16, final 16->1.
//
// Kernel 1: fused  x -> gene -> h0 -> h1   per (row-tile of 64, h1-module g of 64)
//   gene layer folded into weights: w0p = Wg*W0 (elementwise over g),
//   bias0[l,h] = sum_j bg[l,j]*W0[l,j,h]. h1 written to __device__ scratch.
// Kernel 2: h1 -> h2 -> root -> final, 16 rows per block.

#define NINP 4096
#define B_TOT 4096

__device__ float g_h1[(size_t)B_TOT * 1024];

__device__ __forceinline__ float sigmoidf(float z) {
    return __fdividef(1.0f, 1.0f + __expf(-z));
}

// ---------------------------------------------------------------------------
// K1: grid (64 row-tiles, 64 groups), 512 threads = 32 r-slots x 16 h.
// Each thread handles rows (row0+r) and (row0+r+32) for its h.
// ---------------------------------------------------------------------------
__global__ __launch_bounds__(512) void k1(
    const float* __restrict__ x, const float* __restrict__ Wg,
    const float* __restrict__ bgp, const float* __restrict__ W0,
    const float* __restrict__ W1)
{
    __shared__ __align__(16) float h0b[64 * 132];   // [row][l*16+h], pad 132
    __shared__ __align__(16) float w0p[1024];       // fused gene*W0, [(l*8+j)*16+h]
    __shared__ __align__(16) float bias0[128];      // [l*16+h]
    __shared__ __align__(16) float w1t[16 * 132];   // transposed W1 [h][k], pad 132

    const int g    = blockIdx.y;
    const int row0 = blockIdx.x * 64;
    const int tid  = threadIdx.x;
    const int r    = tid >> 4;    // 0..31
    const int h    = tid & 15;    // 0..15

    // --- stage w0p = W0[g] * Wg[g] (2 elems/thread; both share same (l,j)) ---
    {
        const float2 w2 = ((const float2*)(W0 + (size_t)g * 1024))[tid];
        const float wgv = Wg[g * 64 + (tid >> 3)];
        float2 o; o.x = w2.x * wgv; o.y = w2.y * wgv;
        ((float2*)w0p)[tid] = o;
    }
    // --- stage w1t transposed: W1[g] is [k=128][h=16] -> w1t[h][k] ---
    {
        float4 v = ((const float4*)(W1 + (size_t)g * 2048))[tid];
        int i = tid * 4, k = i >> 4, hh = i & 15;
        w1t[(hh + 0) * 132 + k] = v.x;
        w1t[(hh + 1) * 132 + k] = v.y;
        w1t[(hh + 2) * 132 + k] = v.z;
        w1t[(hh + 3) * 132 + k] = v.w;
    }
    // --- stage bias0[l*16+h] = sum_j bg[g,l,j] * W0[g,l,j,h] ---
    if (tid < 128) {
        int l = tid >> 4, hh = tid & 15;
        const float* bgl = bgp + g * 64 + l * 8;
        const float* w0l = W0 + (size_t)g * 1024 + l * 128 + hh;
        float a = 0.f;
        #pragma unroll
        for (int j = 0; j < 8; j++) a += bgl[j] * w0l[j * 16];
        bias0[tid] = a;
    }
    __syncthreads();

    // --- h0: per (row, leaf l): sigmoid(bias0 + x·w0p), x straight from gmem ---
    #pragma unroll
    for (int rr = 0; rr < 2; rr++) {
        const int rw = r + rr * 32;
        const float4* xr = (const float4*)(x + (size_t)(row0 + rw) * NINP + g * 64);
        #pragma unroll
        for (int l = 0; l < 8; l++) {
            const float* w = w0p + l * 128 + h;     // stride 16 over j; 16 h lanes -> 16 banks
            float4 xa = xr[l * 2], xb = xr[l * 2 + 1];
            float acc = bias0[l * 16 + h];
            acc += xa.x * w[0]   + xa.y * w[16]  + xa.z * w[32]  + xa.w * w[48];
            acc += xb.x * w[64]  + xb.y * w[80]  + xb.z * w[96]  + xb.w * w[112];
            h0b[rw * 132 + l * 16 + h] = sigmoidf(acc);
        }
    }
    __syncthreads();

    // --- h1: (row, h) = sigmoid( h0row[0:128] · W1[g,:,h] ), 2 rows/thread ---
    {
        const float4* wv4 = (const float4*)(w1t + h * 132);
        const float4* a0  = (const float4*)(h0b + r * 132);
        const float4* a1  = (const float4*)(h0b + (r + 32) * 132);
        float acc0 = 0.f, acc1 = 0.f;
        #pragma unroll
        for (int k4 = 0; k4 < 32; k4++) {
            float4 w = wv4[k4], v0 = a0[k4], v1 = a1[k4];
            acc0 += v0.x * w.x + v0.y * w.y + v0.z * w.z + v0.w * w.w;
            acc1 += v1.x * w.x + v1.y * w.y + v1.z * w.z + v1.w * w.w;
        }
        g_h1[(size_t)(row0 + r)      * 1024 + g * 16 + h] = sigmoidf(acc0);
        g_h1[(size_t)(row0 + r + 32) * 1024 + g * 16 + h] = sigmoidf(acc1);
    }
}

// ---------------------------------------------------------------------------
// K2: grid 256 blocks x 16 rows, 256 threads = 16 r x 16 h.
// h2 (8 modules, 128->16), root (128->16), final dot(16).
// ---------------------------------------------------------------------------
__global__ __launch_bounds__(256) void k2(
    const float* __restrict__ W2, const float* __restrict__ W3,
    const float* __restrict__ Wf, float* __restrict__ out)
{
    __shared__ __align__(16) float w2t[16 * 132];   // per-module transposed W2
    __shared__ __align__(16) float w3t[16 * 132];
    __shared__ __align__(16) float h2s[16 * 132];   // [r][m*16+h]

    const int row0 = blockIdx.x * 16;
    const int tid  = threadIdx.x;
    const int r    = tid >> 4;
    const int h    = tid & 15;

    // stage w3t once (W3 is [k=128][h=16])
    #pragma unroll
    for (int t = 0; t < 2; t++) {
        int i4 = tid + 256 * t;
        float4 v = ((const float4*)W3)[i4];
        int i = i4 * 4, k = i >> 4, hh = i & 15;
        w3t[(hh + 0) * 132 + k] = v.x;
        w3t[(hh + 1) * 132 + k] = v.y;
        w3t[(hh + 2) * 132 + k] = v.z;
        w3t[(hh + 3) * 132 + k] = v.w;
    }

    const float4* hrow = (const float4*)(g_h1 + (size_t)(row0 + r) * 1024);

    for (int m = 0; m < 8; m++) {
        __syncthreads();   // protect w2t from previous iteration's readers
        #pragma unroll
        for (int t = 0; t < 2; t++) {
            int i4 = tid + 256 * t;
            float4 v = ((const float4*)(W2 + (size_t)m * 2048))[i4];
            int i = i4 * 4, k = i >> 4, hh = i & 15;
            w2t[(hh + 0) * 132 + k] = v.x;
            w2t[(hh + 1) * 132 + k] = v.y;
            w2t[(hh + 2) * 132 + k] = v.z;
            w2t[(hh + 3) * 132 + k] = v.w;
        }
        __syncthreads();
        const float4* wv4 = (const float4*)(w2t + h * 132);
        float acc = 0.f;
        #pragma unroll
        for (int k4 = 0; k4 < 32; k4++) {
            float4 w = wv4[k4], v = hrow[m * 32 + k4];
            acc += v.x * w.x + v.y * w.y + v.z * w.z + v.w * w.w;
        }
        h2s[r * 132 + m * 16 + h] = sigmoidf(acc);
    }
    __syncthreads();

    // root + final
    {
        const float4* a   = (const float4*)(h2s + r * 132);
        const float4* wv4 = (const float4*)(w3t + h * 132);
        float acc = 0.f;
        #pragma unroll
        for (int k4 = 0; k4 < 32; k4++) {
            float4 w = wv4[k4], v = a[k4];
            acc += v.x * w.x + v.y * w.y + v.z * w.z + v.w * w.w;
        }
        float yv = sigmoidf(acc) * Wf[h];
        #pragma unroll
        for (int off = 8; off; off >>= 1)
            yv += __shfl_xor_sync(0xffffffffu, yv, off);
        if (h == 0) out[row0 + r] = yv;
    }
}

extern "C" void kernel_launch(void* const* d_in, const int* in_sizes, int n_in,
                              void* d_out, int out_size)
{
    const float* x  = (const float*)d_in[0];
    const float* Wg = (const float*)d_in[1];
    const float* bg = (const float*)d_in[2];
    const float* W0 = (const float*)d_in[3];
    const float* W1 = (const float*)d_in[4];
    const float* W2 = (const float*)d_in[5];
    const float* W3 = (const float*)d_in[6];
    const float* Wf = (const float*)d_in[7];
    float* out = (float*)d_out;

    dim3 g1(B_TOT / 64, 64);
    k1<<<g1, 512>>>(x, Wg, bg, W0, W1);
    k2<<<B_TOT / 16, 256>>>(W2, W3, Wf, out);
}